// round 16
// baseline (speedup 1.0000x reference)
#include <cuda_runtime.h>
#include <cuda_bf16.h>
#include <stdint.h>

// Problem constants
#define B_ 8
#define N_ 512
#define D_ 768
#define A_ 12
#define E_ 64
#define M_ (B_ * N_)   // 4096

// ---------------------------------------------------------------------------
// PTX helpers (baseline features only)
// ---------------------------------------------------------------------------
__device__ __forceinline__ uint32_t smem_u32(const void* p) {
    uint32_t a;
    asm("{ .reg .u64 t; cvta.to.shared.u64 t, %1; cvt.u32.u64 %0, t; }" : "=r"(a) : "l"(p));
    return a;
}
__device__ __forceinline__ void ldsm_x4(uint32_t* r, uint32_t addr) {
    asm volatile("ldmatrix.sync.aligned.m8n8.x4.shared.b16 {%0,%1,%2,%3}, [%4];"
        : "=r"(r[0]), "=r"(r[1]), "=r"(r[2]), "=r"(r[3]) : "r"(addr));
}
__device__ __forceinline__ void ldsm_x4_t(uint32_t* r, uint32_t addr) {
    asm volatile("ldmatrix.sync.aligned.m8n8.x4.trans.shared.b16 {%0,%1,%2,%3}, [%4];"
        : "=r"(r[0]), "=r"(r[1]), "=r"(r[2]), "=r"(r[3]) : "r"(addr));
}
#define CP16(dst, src) asm volatile("cp.async.cg.shared.global [%0], [%1], 16;" :: "r"(dst), "l"(src))
#define CP_COMMIT() asm volatile("cp.async.commit_group;" ::: "memory")
#define CP_WAIT0() asm volatile("cp.async.wait_group 0;" ::: "memory")

__device__ __forceinline__ void mma16816(float* c,
        uint32_t a0, uint32_t a1, uint32_t a2, uint32_t a3,
        uint32_t b0, uint32_t b1) {
    asm volatile(
        "mma.sync.aligned.m16n8k16.row.col.f32.bf16.bf16.f32 "
        "{%0,%1,%2,%3}, {%4,%5,%6,%7}, {%8,%9}, {%0,%1,%2,%3};"
        : "+f"(c[0]), "+f"(c[1]), "+f"(c[2]), "+f"(c[3])
        : "r"(a0), "r"(a1), "r"(a2), "r"(a3), "r"(b0), "r"(b1));
}

// ---------------------------------------------------------------------------
// Scratch (device globals: allocation-free)
// ---------------------------------------------------------------------------
__device__ float g_src[B_ * A_ * N_];
__device__ float g_dst[B_ * A_ * N_];
__device__ float g_gate[B_ * N_ * D_];
__device__ int   g_adj_int;
__device__ __align__(16) __nv_bfloat16 g_hbh[B_ * A_ * N_ * E_];
__device__ __align__(16) __nv_bfloat16 g_hbl[B_ * A_ * N_ * E_];
__device__ __align__(16) __nv_bfloat16 g_fh[M_ * D_];
__device__ __align__(16) __nv_bfloat16 g_fl[M_ * D_];
__device__ __align__(16) __nv_bfloat16 g_w1h[D_ * D_];
__device__ __align__(16) __nv_bfloat16 g_w1l[D_ * D_];
__device__ __align__(16) __nv_bfloat16 g_w2h[D_ * D_];

// ---------------------------------------------------------------------------
__device__ __forceinline__ void split2(float x, __nv_bfloat16& h, __nv_bfloat16& l) {
    h = __float2bfloat16(x);
    l = __float2bfloat16(x - __bfloat162float(h));
}

// ---------------------------------------------------------------------------
// Combined prep kernel (unchanged)
// ---------------------------------------------------------------------------
#define PREP_FEAT 3072
#define PREP_W2 (PREP_FEAT + 576)
#define PREP_W1 (PREP_W2 + 144)
#define PREP_GRID (PREP_W1 + 1)

__global__ void prep_kernel(const float* __restrict__ f, const float* __restrict__ W,
                            const float* __restrict__ Hw, const int* __restrict__ adj) {
    __shared__ float tile[64][65];
    const int bx = blockIdx.x;
    const int tid = threadIdx.x;
    if (bx < PREP_FEAT) {
        const int g4 = (bx * 256 + tid) * 4;
        float4 v = *(const float4*)(f + g4);
        __nv_bfloat16 h0, h1, h2, h3, l0, l1, l2, l3;
        split2(v.x, h0, l0); split2(v.y, h1, l1); split2(v.z, h2, l2); split2(v.w, h3, l3);
        ((__nv_bfloat162*)(g_fh + g4))[0] = __nv_bfloat162(h0, h1);
        ((__nv_bfloat162*)(g_fh + g4))[1] = __nv_bfloat162(h2, h3);
        ((__nv_bfloat162*)(g_fl + g4))[0] = __nv_bfloat162(l0, l1);
        ((__nv_bfloat162*)(g_fl + g4))[1] = __nv_bfloat162(l2, l3);
    } else if (bx < PREP_W2) {
        const int g4 = ((bx - PREP_FEAT) * 256 + tid) * 4;
        float4 v = *(const float4*)(Hw + g4);
        __nv_bfloat16 h0 = __float2bfloat16(v.x), h1 = __float2bfloat16(v.y);
        __nv_bfloat16 h2 = __float2bfloat16(v.z), h3 = __float2bfloat16(v.w);
        ((__nv_bfloat162*)(g_w2h + g4))[0] = __nv_bfloat162(h0, h1);
        ((__nv_bfloat162*)(g_w2h + g4))[1] = __nv_bfloat162(h2, h3);
    } else if (bx < PREP_W1) {
        const int idx0 = bx - PREP_W2;
        const int a = idx0 / (D_ / 64), d0 = (idx0 % (D_ / 64)) * 64;
#pragma unroll
        for (int it = 0; it < 16; ++it) {
            const int idx = it * 256 + tid;
            const int dd = idx >> 6, e = idx & 63;
            tile[dd][e] = W[(a * D_ + d0 + dd) * E_ + e];
        }
        __syncthreads();
#pragma unroll
        for (int it = 0; it < 16; ++it) {
            const int idx = it * 256 + tid;
            const int e = idx >> 6, dd = idx & 63;
            __nv_bfloat16 h, l;
            split2(tile[dd][e], h, l);
            g_w1h[(a * 64 + e) * D_ + d0 + dd] = h;
            g_w1l[(a * 64 + e) * D_ + d0 + dd] = l;
        }
    } else {
        if (tid < 32) {
            int ok = 1;
            for (int v = tid; v < 1024; v += 32) {
                int w = adj[v];
                if (w != 0 && w != 1) ok = 0;
            }
#pragma unroll
            for (int o = 16; o; o >>= 1) ok &= __shfl_xor_sync(0xffffffffu, ok, o);
            if (tid == 0) g_adj_int = ok;
        }
    }
}

// ---------------------------------------------------------------------------
// HMMA bf16 GEMM mainloop: 128x64 block tile, 8 warps (4m x 2n), warp 32x32.
// Single sync per chunk; cp.async double buffer.
// ---------------------------------------------------------------------------
#define KC_ 32
#define NKC_ (D_ / KC_)          // 24
#define TROW_B 80
#define TILEA_B (128 * TROW_B)   // 10240
#define TILEB_B (64 * TROW_B)    // 5120
#define BUF_B (2 * TILEA_B + 2 * TILEB_B)  // 30720
#define GEMM_SMEM (2 * BUF_B)    // 61440

template <bool USE_BL>
__device__ __forceinline__ void hmma_mainloop(
        float acc[2][4][4],
        const __nv_bfloat16* __restrict__ Ah, const __nv_bfloat16* __restrict__ Al,
        const __nv_bfloat16* __restrict__ Bh, const __nv_bfloat16* __restrict__ Bl,
        int m0, int n0, char* sm) {
    const int tid = threadIdx.x;
    const int warp = tid >> 5, lane = tid & 31;
    const int wm = warp & 3, wn = warp >> 2;

    const int lrA = tid >> 1;
    const uint32_t stoA = (uint32_t)lrA * TROW_B + (tid & 1) * 32;
    const int lrB = tid >> 2;
    const uint32_t stoB = (uint32_t)lrB * TROW_B + (tid & 3) * 16;
    const uint32_t smu = smem_u32(sm);

    const __nv_bfloat16* pAh = Ah + (size_t)(m0 + lrA) * D_ + (tid & 1) * 16;
    const __nv_bfloat16* pAl = Al + (size_t)(m0 + lrA) * D_ + (tid & 1) * 16;
    const __nv_bfloat16* pBh = Bh + (size_t)(n0 + lrB) * D_ + (tid & 3) * 8;
    const __nv_bfloat16* pBl = USE_BL ? (Bl + (size_t)(n0 + lrB) * D_ + (tid & 3) * 8) : pBh;

#define ISSUE(kc, buf) do {                                                  \
    uint32_t _bb = smu + (buf) * BUF_B;                                      \
    const int _o = (kc) * KC_;                                               \
    CP16(_bb + stoA, pAh + _o);            CP16(_bb + stoA + 16, pAh + _o + 8); \
    CP16(_bb + TILEA_B + stoA, pAl + _o);  CP16(_bb + TILEA_B + stoA + 16, pAl + _o + 8); \
    CP16(_bb + 2 * TILEA_B + stoB, pBh + _o);                                \
    if (USE_BL) CP16(_bb + 2 * TILEA_B + TILEB_B + stoB, pBl + _o);          \
    CP_COMMIT(); } while (0)

    ISSUE(0, 0);

    const int arow = (lane & 7) + ((lane >> 3) & 1) * 8;
    const int acolb = (lane >> 4) * 16;
    const int brow = (lane & 7) + (lane >> 4) * 8;
    const int bcolb = ((lane >> 3) & 1) * 16;

    for (int kc = 0; kc < NKC_; ++kc) {
        CP_WAIT0();
        __syncthreads();
        const uint32_t bufb = smu + (kc & 1) * BUF_B;
        const uint32_t aA0 = bufb + (uint32_t)(wm * 32 + arow) * TROW_B + acolb;
        const uint32_t bB0 = bufb + 2 * TILEA_B + (uint32_t)(wn * 32 + brow) * TROW_B + bcolb;
#pragma unroll
        for (int ks = 0; ks < 2; ++ks) {
            uint32_t ah[2][4], al[2][4], bh[2][4], bl[2][4];
#pragma unroll
            for (int mf = 0; mf < 2; ++mf) {
                ldsm_x4(ah[mf], aA0 + mf * 16 * TROW_B + ks * 32);
                ldsm_x4(al[mf], aA0 + TILEA_B + mf * 16 * TROW_B + ks * 32);
            }
#pragma unroll
            for (int nfp = 0; nfp < 2; ++nfp) {
                ldsm_x4(bh[nfp], bB0 + nfp * 16 * TROW_B + ks * 32);
                if (USE_BL) ldsm_x4(bl[nfp], bB0 + TILEB_B + nfp * 16 * TROW_B + ks * 32);
            }
            if (ks == 0 && kc + 1 < NKC_) ISSUE(kc + 1, (kc + 1) & 1);
#pragma unroll
            for (int nfp = 0; nfp < 2; ++nfp)
#pragma unroll
                for (int hf = 0; hf < 2; ++hf) {
                    const int nf = nfp * 2 + hf;
                    const uint32_t b0h = bh[nfp][hf * 2], b1h = bh[nfp][hf * 2 + 1];
#pragma unroll
                    for (int mf = 0; mf < 2; ++mf) {
                        mma16816(acc[mf][nf], ah[mf][0], ah[mf][1], ah[mf][2], ah[mf][3], b0h, b1h);
                        mma16816(acc[mf][nf], al[mf][0], al[mf][1], al[mf][2], al[mf][3], b0h, b1h);
                        if (USE_BL)
                            mma16816(acc[mf][nf], ah[mf][0], ah[mf][1], ah[mf][2], ah[mf][3],
                                     bl[nfp][hf * 2], bl[nfp][hf * 2 + 1]);
                    }
                }
        }
    }
    __syncthreads();
#undef ISSUE
}

// ---------------------------------------------------------------------------
// Combined GEMM kernel (128x64 tiles): z=0 -> h GEMM; z=1 -> gate GEMM.
// grid = (12, 32, 2)
// ---------------------------------------------------------------------------
__global__ __launch_bounds__(256, 2) void gemm_all_kernel(const float* __restrict__ wsrc,
                                                          const float* __restrict__ wdst,
                                                          const float* __restrict__ Hb) {
    extern __shared__ char sm[];
    const int m0 = blockIdx.y << 7;
    const int n0 = blockIdx.x << 6;
    float acc[2][4][4];
#pragma unroll
    for (int mf = 0; mf < 2; ++mf)
#pragma unroll
        for (int nf = 0; nf < 4; ++nf)
#pragma unroll
            for (int q = 0; q < 4; ++q) acc[mf][nf][q] = 0.f;

    const int warp = threadIdx.x >> 5, lane = threadIdx.x & 31;
    const int wm = warp & 3, wn = warp >> 2;
    const int g = lane >> 2, t = lane & 3;

    if (blockIdx.z == 0) {
        hmma_mainloop<true>(acc, g_fh, g_fl, g_w1h, g_w1l, m0, n0, sm);
        const int head = blockIdx.x;            // n-tile == one head
        float* s_red = (float*)sm;              // [2 wn][128] src, then dst at +256
        float sd[2][2], dd[2][2];
#pragma unroll
        for (int mf = 0; mf < 2; ++mf) sd[mf][0] = sd[mf][1] = dd[mf][0] = dd[mf][1] = 0.f;
#pragma unroll
        for (int mf = 0; mf < 2; ++mf) {
            const int m = m0 + wm * 32 + mf * 16 + g;
            const int b = m >> 9, i = m & (N_ - 1);
            const int ba = b * A_ + head;
#pragma unroll
            for (int nf = 0; nf < 4; ++nf) {
                const int e = wn * 32 + nf * 8 + 2 * t;
                __nv_bfloat16 h0, l0, h1, l1;
                split2(acc[mf][nf][0], h0, l0);
                split2(acc[mf][nf][1], h1, l1);
                *(__nv_bfloat162*)&g_hbh[((size_t)(ba * N_ + i)) * E_ + e] = __nv_bfloat162(h0, h1);
                *(__nv_bfloat162*)&g_hbl[((size_t)(ba * N_ + i)) * E_ + e] = __nv_bfloat162(l0, l1);
                split2(acc[mf][nf][2], h0, l0);
                split2(acc[mf][nf][3], h1, l1);
                *(__nv_bfloat162*)&g_hbh[((size_t)(ba * N_ + i + 8)) * E_ + e] = __nv_bfloat162(h0, h1);
                *(__nv_bfloat162*)&g_hbl[((size_t)(ba * N_ + i + 8)) * E_ + e] = __nv_bfloat162(l0, l1);
                float2 ws = *(const float2*)(wsrc + head * E_ + e);
                float2 wd = *(const float2*)(wdst + head * E_ + e);
                float t0 = tanhf(acc[mf][nf][0]), t1 = tanhf(acc[mf][nf][1]);
                float t2 = tanhf(acc[mf][nf][2]), t3 = tanhf(acc[mf][nf][3]);
                sd[mf][0] += t0 * ws.x + t1 * ws.y;
                sd[mf][1] += t2 * ws.x + t3 * ws.y;
                dd[mf][0] += t0 * wd.x + t1 * wd.y;
                dd[mf][1] += t2 * wd.x + t3 * wd.y;
            }
#pragma unroll
            for (int rh = 0; rh < 2; ++rh) {
                float s = sd[mf][rh], d = dd[mf][rh];
                s += __shfl_xor_sync(0xffffffffu, s, 1);
                s += __shfl_xor_sync(0xffffffffu, s, 2);
                d += __shfl_xor_sync(0xffffffffu, d, 1);
                d += __shfl_xor_sync(0xffffffffu, d, 2);
                if (t == 0) {
                    const int rowloc = wm * 32 + mf * 16 + rh * 8 + g;
                    s_red[wn * 128 + rowloc] = s;
                    s_red[256 + wn * 128 + rowloc] = d;
                }
            }
        }
        __syncthreads();
        if (threadIdx.x < 128) {
            const int row = threadIdx.x;
            const int m = m0 + row;
            const int b = m >> 9, i = m & (N_ - 1);
            const int ba = b * A_ + head;
            g_src[ba * N_ + i] = s_red[row] + s_red[128 + row];
            g_dst[ba * N_ + i] = s_red[256 + row] + s_red[384 + row];
        }
    } else {
        hmma_mainloop<false>(acc, g_fh, g_fl, g_w2h, g_w2h, m0, n0, sm);
#pragma unroll
        for (int mf = 0; mf < 2; ++mf)
#pragma unroll
            for (int nf = 0; nf < 4; ++nf) {
                const int m = m0 + wm * 32 + mf * 16 + g;
                const int n = n0 + wn * 32 + nf * 8 + 2 * t;
                float2 hb = *(const float2*)(Hb + n);
#pragma unroll
                for (int rr = 0; rr < 2; ++rr) {
                    const int mm = m + rr * 8;
                    float2 gv;
                    gv.x = 1.f / (1.f + __expf(-(acc[mf][nf][rr * 2 + 0] + hb.x)));
                    gv.y = 1.f / (1.f + __expf(-(acc[mf][nf][rr * 2 + 1] + hb.y)));
                    *(float2*)(g_gate + (size_t)mm * D_ + n) = gv;
                }
            }
    }
}

// ---------------------------------------------------------------------------
// Attention (HMMA, i-tile 64, double-buffered P, 1 sync/chunk) + fused blend.
// ---------------------------------------------------------------------------
#define IT_ 64
#define HC_ROWB 144
#define HC_BUF_B (64 * HC_ROWB)          // 9216
#define P_ROWB 144
#define P_BUF_B (64 * P_ROWB)            // 9216
#define OFF_HCH 0                        // 2 bufs: 18432
#define OFF_HCL 18432                    // 2 bufs: 18432
#define OFF_PBH 36864                    // 2 bufs: 18432
#define OFF_PBL 55296                    // 2 bufs: 18432
#define OFF_SRC 73728                    // 256
#define OFF_DST 73984                    // 2048
#define OFF_MS  76032                    // 4096
#define OFF_SUM 80128                    // 256
#define ATT_SMEM_B 80384

__global__ __launch_bounds__(256, 2) void attn_kernel(const void* __restrict__ adjv,
                                                      const float* __restrict__ bbias,
                                                      const float* __restrict__ feat,
                                                      float* __restrict__ out) {
    extern __shared__ char sm[];
    const uint32_t smu = smem_u32(sm);
    char* Pbh = sm + OFF_PBH;
    char* Pbl = sm + OFF_PBL;
    float* s_src = (float*)(sm + OFF_SRC);
    float* s_dst = (float*)(sm + OFF_DST);
    float* s_sum = (float*)(sm + OFF_SUM);
    unsigned short* Ms = (unsigned short*)(sm + OFF_MS);   // [32 jwords][64 rows]

    const int tid = threadIdx.x;
    const int lane = tid & 31, warp = tid >> 5;
    const int b = blockIdx.z, a = blockIdx.y, it = blockIdx.x;
    const int ba = b * A_ + a;
    const int i0 = it * IT_;

    const __nv_bfloat16* srcH = g_hbh + (size_t)ba * N_ * E_;
    const __nv_bfloat16* srcL = g_hbl + (size_t)ba * N_ * E_;

#define ISSUE_H(jc, buf) do {                                                \
    const int _j0 = (jc) * 64;                                               \
    _Pragma("unroll")                                                        \
    for (int _c = 0; _c < 2; ++_c) {                                         \
        const int _idx = tid * 2 + _c;                                       \
        const int _jr = _idx >> 3, _q = _idx & 7;                            \
        const uint32_t _dst = smu + OFF_HCH + (buf) * HC_BUF_B + _jr * HC_ROWB + _q * 16; \
        CP16(_dst, srcH + (size_t)(_j0 + _jr) * E_ + _q * 8);                \
        CP16(_dst + (OFF_HCL - OFF_HCH), srcL + (size_t)(_j0 + _jr) * E_ + _q * 8); \
    }                                                                        \
    CP_COMMIT(); } while (0)

    // ---- Phase A ----
    ISSUE_H(0, 0);
    if (tid < IT_) s_src[tid] = g_src[ba * N_ + i0 + tid];
    s_dst[tid] = g_dst[ba * N_ + tid];
    s_dst[tid + 256] = g_dst[ba * N_ + tid + 256];
    __syncthreads();

    // ---- Phase B: mask bits ----
    const int adj_int = g_adj_int;
    for (int rr = warp; rr < IT_; rr += 8) {
        const size_t rowoff = (size_t)(b * N_ + i0 + rr) * N_;
        unsigned mbits = 0;
        if (adj_int) {
            const uint4* ap = (const uint4*)((const int*)adjv + rowoff + lane * 16);
#pragma unroll
            for (int q = 0; q < 4; ++q) {
                uint4 w = ap[q];
                mbits |= (w.x ? 1u : 0u) << (q * 4 + 0);
                mbits |= (w.y ? 1u : 0u) << (q * 4 + 1);
                mbits |= (w.z ? 1u : 0u) << (q * 4 + 2);
                mbits |= (w.w ? 1u : 0u) << (q * 4 + 3);
            }
        } else {
            uint4 w = *(const uint4*)((const uint8_t*)adjv + rowoff + lane * 16);
            unsigned ws[4] = {w.x, w.y, w.z, w.w};
#pragma unroll
            for (int q = 0; q < 4; ++q)
#pragma unroll
                for (int bq = 0; bq < 4; ++bq)
                    mbits |= (((ws[q] >> (8 * bq)) & 0xffu) ? 1u : 0u) << (q * 4 + bq);
        }
        Ms[lane * IT_ + rr] = (unsigned short)mbits;
    }
    __syncthreads();

    // ---- Phase C: pipelined P-gen / HMMA ----
    const int wm = warp & 1, wn = warp >> 1;
    const int r = tid >> 2, jseg = (tid & 3) * 16;
    const float srcv = s_src[r];

    const int arow = (lane & 7) + ((lane >> 3) & 1) * 8;
    const int acolb = (lane >> 4) * 16;
    const uint32_t aP0 = smu + OFF_PBH + (uint32_t)(wm * 32 + arow) * P_ROWB + acolb;
    const int jrow = lane & 15;
    const int ecolb = (lane >> 4) * 16;
    const uint32_t bH0 = smu + OFF_HCH + (uint32_t)jrow * HC_ROWB + (wn * 16) * 2 + ecolb;

    float acc[2][2][4];
#pragma unroll
    for (int mf = 0; mf < 2; ++mf)
#pragma unroll
        for (int nf = 0; nf < 2; ++nf)
#pragma unroll
            for (int q = 0; q < 4; ++q) acc[mf][nf][q] = 0.f;

    float psum = 0.f;

    auto pgen = [&](int jc, int buf) {
        const int jb = jc * 64 + jseg;
        uint32_t mbits = Ms[(jb >> 4) * IT_ + r];
        char* ph = Pbh + buf * P_BUF_B + r * P_ROWB;
        char* pl = Pbl + buf * P_BUF_B + r * P_ROWB;
#pragma unroll
        for (int q = 0; q < 16; q += 4) {
            float4 dv = *(const float4*)&s_dst[jb + q];
            float p[4];
#pragma unroll
            for (int e = 0; e < 4; ++e) {
                float v = srcv + (&dv.x)[e];
                v = v >= 0.f ? v : 0.2f * v;
                p[e] = ((mbits >> (q + e)) & 1u) ? __expf(v) : 0.f;
                psum += p[e];
            }
            __nv_bfloat16 h0, l0, h1, l1;
            split2(p[0], h0, l0); split2(p[1], h1, l1);
            *(__nv_bfloat162*)(ph + (jseg + q) * 2) = __nv_bfloat162(h0, h1);
            *(__nv_bfloat162*)(pl + (jseg + q) * 2) = __nv_bfloat162(l0, l1);
            split2(p[2], h0, l0); split2(p[3], h1, l1);
            *(__nv_bfloat162*)(ph + (jseg + q + 2) * 2) = __nv_bfloat162(h0, h1);
            *(__nv_bfloat162*)(pl + (jseg + q + 2) * 2) = __nv_bfloat162(l0, l1);
        }
    };

    pgen(0, 0);

    for (int jc = 0; jc < 8; ++jc) {
        CP_WAIT0();            // own copies of H[jc] done
        __syncthreads();       // everyone's copies done; prior reads of opposite bufs retired
        if (jc + 1 < 8) {
            ISSUE_H(jc + 1, (jc + 1) & 1);
            pgen(jc + 1, (jc + 1) & 1);
        }
        const uint32_t pb = (jc & 1) * P_BUF_B;
        const uint32_t bbuf = bH0 + (jc & 1) * HC_BUF_B;
#pragma unroll
        for (int ks = 0; ks < 4; ++ks) {
            uint32_t ah[2][4], al[2][4], bh[4], bl[4];
#pragma unroll
            for (int mf = 0; mf < 2; ++mf) {
                ldsm_x4(ah[mf], aP0 + pb + mf * 16 * P_ROWB + ks * 32);
                ldsm_x4(al[mf], aP0 + pb + (OFF_PBL - OFF_PBH) + mf * 16 * P_ROWB + ks * 32);
            }
            const uint32_t bbase = bbuf + (uint32_t)(ks * 16) * HC_ROWB;
            ldsm_x4_t(bh, bbase);
            ldsm_x4_t(bl, bbase + (OFF_HCL - OFF_HCH));
#pragma unroll
            for (int nf = 0; nf < 2; ++nf) {
                const uint32_t b0h = bh[nf * 2], b1h = bh[nf * 2 + 1];
                const uint32_t b0l = bl[nf * 2], b1l = bl[nf * 2 + 1];
#pragma unroll
                for (int mf = 0; mf < 2; ++mf) {
                    mma16816(acc[mf][nf], ah[mf][0], ah[mf][1], ah[mf][2], ah[mf][3], b0h, b1h);
                    mma16816(acc[mf][nf], al[mf][0], al[mf][1], al[mf][2], al[mf][3], b0h, b1h);
                    mma16816(acc[mf][nf], ah[mf][0], ah[mf][1], ah[mf][2], ah[mf][3], b0l, b1l);
                }
            }
        }
    }
#undef ISSUE_H

    // row-sum: quad-reduce and publish
    psum += __shfl_xor_sync(0xffffffffu, psum, 1);
    psum += __shfl_xor_sync(0xffffffffu, psum, 2);
    if ((tid & 3) == 0) s_sum[r] = psum;
    __syncthreads();

    // ---- epilogue: normalize + bias + elu + highway blend -> d_out ----
    const int g = lane >> 2, t = lane & 3;
#pragma unroll
    for (int mf = 0; mf < 2; ++mf) {
        const int rl = wm * 32 + mf * 16 + g;
        const float inv0 = __fdividef(1.f, s_sum[rl]);
        const float inv1 = __fdividef(1.f, s_sum[rl + 8]);
#pragma unroll
        for (int nf = 0; nf < 2; ++nf) {
            const int col = wn * 16 + nf * 8 + 2 * t;
            const int n = a * E_ + col;
            float2 bias = *(const float2*)(bbias + col);
#pragma unroll
            for (int rr = 0; rr < 2; ++rr) {
                const int row = i0 + rl + rr * 8;
                const size_t off = (size_t)(b * N_ + row) * D_ + n;
                const float inv = rr ? inv1 : inv0;
                float2 gv = *(const float2*)(g_gate + off);
                float2 fv = *(const float2*)(feat + off);
                float a0 = fmaf(acc[mf][nf][rr * 2 + 0], inv, bias.x);
                float a1 = fmaf(acc[mf][nf][rr * 2 + 1], inv, bias.y);
                float fo0 = a0 > 0.f ? a0 : (__expf(a0) - 1.f);
                float fo1 = a1 > 0.f ? a1 : (__expf(a1) - 1.f);
                float2 ov;
                ov.x = gv.x * fo0 + (1.f - gv.x) * fv.x;
                ov.y = gv.y * fo1 + (1.f - gv.y) * fv.y;
                *(float2*)(out + off) = ov;
            }
        }
    }
}

// ---------------------------------------------------------------------------
extern "C" void kernel_launch(void* const* d_in, const int* in_sizes, int n_in,
                              void* d_out, int out_size) {
    const float* feat = (const float*)d_in[0];
    const void* adj = d_in[1];
    const float* W = (const float*)d_in[2];
    const float* bbias = (const float*)d_in[3];
    const float* wsrc = (const float*)d_in[4];
    const float* wdst = (const float*)d_in[5];
    const float* Hw = (const float*)d_in[6];
    const float* Hb = (const float*)d_in[7];
    float* out = (float*)d_out;

    prep_kernel<<<PREP_GRID, 256>>>(feat, W, Hw, (const int*)adj);

    cudaFuncSetAttribute(gemm_all_kernel, cudaFuncAttributeMaxDynamicSharedMemorySize, GEMM_SMEM);
    cudaFuncSetAttribute(attn_kernel, cudaFuncAttributeMaxDynamicSharedMemorySize, ATT_SMEM_B);

    gemm_all_kernel<<<dim3(D_ / 64, M_ / 128, 2), 256, GEMM_SMEM>>>(wsrc, wdst, Hb);

    attn_kernel<<<dim3(N_ / IT_, A_, B_), 256, ATT_SMEM_B>>>(adj, bbias, feat, out);
}

// round 17
// speedup vs baseline: 1.0137x; 1.0137x over previous
#include <cuda_runtime.h>
#include <cuda_bf16.h>
#include <stdint.h>

// Problem constants
#define B_ 8
#define N_ 512
#define D_ 768
#define A_ 12
#define E_ 64
#define M_ (B_ * N_)   // 4096

// ---------------------------------------------------------------------------
// PTX helpers (baseline features only)
// ---------------------------------------------------------------------------
__device__ __forceinline__ uint32_t smem_u32(const void* p) {
    uint32_t a;
    asm("{ .reg .u64 t; cvta.to.shared.u64 t, %1; cvt.u32.u64 %0, t; }" : "=r"(a) : "l"(p));
    return a;
}
__device__ __forceinline__ void ldsm_x4(uint32_t* r, uint32_t addr) {
    asm volatile("ldmatrix.sync.aligned.m8n8.x4.shared.b16 {%0,%1,%2,%3}, [%4];"
        : "=r"(r[0]), "=r"(r[1]), "=r"(r[2]), "=r"(r[3]) : "r"(addr));
}
__device__ __forceinline__ void ldsm_x4_t(uint32_t* r, uint32_t addr) {
    asm volatile("ldmatrix.sync.aligned.m8n8.x4.trans.shared.b16 {%0,%1,%2,%3}, [%4];"
        : "=r"(r[0]), "=r"(r[1]), "=r"(r[2]), "=r"(r[3]) : "r"(addr));
}
#define CP16(dst, src) asm volatile("cp.async.cg.shared.global [%0], [%1], 16;" :: "r"(dst), "l"(src))
#define CP_COMMIT() asm volatile("cp.async.commit_group;" ::: "memory")
#define CP_WAIT0() asm volatile("cp.async.wait_group 0;" ::: "memory")

__device__ __forceinline__ void mma16816(float* c,
        uint32_t a0, uint32_t a1, uint32_t a2, uint32_t a3,
        uint32_t b0, uint32_t b1) {
    asm volatile(
        "mma.sync.aligned.m16n8k16.row.col.f32.bf16.bf16.f32 "
        "{%0,%1,%2,%3}, {%4,%5,%6,%7}, {%8,%9}, {%0,%1,%2,%3};"
        : "+f"(c[0]), "+f"(c[1]), "+f"(c[2]), "+f"(c[3])
        : "r"(a0), "r"(a1), "r"(a2), "r"(a3), "r"(b0), "r"(b1));
}

// ---------------------------------------------------------------------------
// Scratch (device globals: allocation-free)
// ---------------------------------------------------------------------------
__device__ float g_src[B_ * A_ * N_];
__device__ float g_dst[B_ * A_ * N_];
__device__ float g_gate[B_ * N_ * D_];
__device__ int   g_adj_int;
__device__ __align__(16) __nv_bfloat16 g_hbh[B_ * A_ * N_ * E_];
__device__ __align__(16) __nv_bfloat16 g_hbl[B_ * A_ * N_ * E_];
__device__ __align__(16) __nv_bfloat16 g_fh[M_ * D_];
__device__ __align__(16) __nv_bfloat16 g_fl[M_ * D_];
__device__ __align__(16) __nv_bfloat16 g_w1h[D_ * D_];
__device__ __align__(16) __nv_bfloat16 g_w1l[D_ * D_];
__device__ __align__(16) __nv_bfloat16 g_w2h[D_ * D_];

// ---------------------------------------------------------------------------
__device__ __forceinline__ void split2(float x, __nv_bfloat16& h, __nv_bfloat16& l) {
    h = __float2bfloat16(x);
    l = __float2bfloat16(x - __bfloat162float(h));
}

// ---------------------------------------------------------------------------
// Combined prep kernel
// ---------------------------------------------------------------------------
#define PREP_FEAT 3072
#define PREP_W2 (PREP_FEAT + 576)
#define PREP_W1 (PREP_W2 + 144)
#define PREP_GRID (PREP_W1 + 1)

__global__ void prep_kernel(const float* __restrict__ f, const float* __restrict__ W,
                            const float* __restrict__ Hw, const int* __restrict__ adj) {
    __shared__ float tile[64][65];
    const int bx = blockIdx.x;
    const int tid = threadIdx.x;
    if (bx < PREP_FEAT) {
        const int g4 = (bx * 256 + tid) * 4;
        float4 v = *(const float4*)(f + g4);
        __nv_bfloat16 h0, h1, h2, h3, l0, l1, l2, l3;
        split2(v.x, h0, l0); split2(v.y, h1, l1); split2(v.z, h2, l2); split2(v.w, h3, l3);
        ((__nv_bfloat162*)(g_fh + g4))[0] = __nv_bfloat162(h0, h1);
        ((__nv_bfloat162*)(g_fh + g4))[1] = __nv_bfloat162(h2, h3);
        ((__nv_bfloat162*)(g_fl + g4))[0] = __nv_bfloat162(l0, l1);
        ((__nv_bfloat162*)(g_fl + g4))[1] = __nv_bfloat162(l2, l3);
    } else if (bx < PREP_W2) {
        const int g4 = ((bx - PREP_FEAT) * 256 + tid) * 4;
        float4 v = *(const float4*)(Hw + g4);
        __nv_bfloat16 h0 = __float2bfloat16(v.x), h1 = __float2bfloat16(v.y);
        __nv_bfloat16 h2 = __float2bfloat16(v.z), h3 = __float2bfloat16(v.w);
        ((__nv_bfloat162*)(g_w2h + g4))[0] = __nv_bfloat162(h0, h1);
        ((__nv_bfloat162*)(g_w2h + g4))[1] = __nv_bfloat162(h2, h3);
    } else if (bx < PREP_W1) {
        const int idx0 = bx - PREP_W2;
        const int a = idx0 / (D_ / 64), d0 = (idx0 % (D_ / 64)) * 64;
#pragma unroll
        for (int it = 0; it < 16; ++it) {
            const int idx = it * 256 + tid;
            const int dd = idx >> 6, e = idx & 63;
            tile[dd][e] = W[(a * D_ + d0 + dd) * E_ + e];
        }
        __syncthreads();
#pragma unroll
        for (int it = 0; it < 16; ++it) {
            const int idx = it * 256 + tid;
            const int e = idx >> 6, dd = idx & 63;
            __nv_bfloat16 h, l;
            split2(tile[dd][e], h, l);
            g_w1h[(a * 64 + e) * D_ + d0 + dd] = h;
            g_w1l[(a * 64 + e) * D_ + d0 + dd] = l;
        }
    } else {
        if (tid < 32) {
            int ok = 1;
            for (int v = tid; v < 1024; v += 32) {
                int w = adj[v];
                if (w != 0 && w != 1) ok = 0;
            }
#pragma unroll
            for (int o = 16; o; o >>= 1) ok &= __shfl_xor_sync(0xffffffffu, ok, o);
            if (tid == 0) g_adj_int = ok;
        }
    }
}

// ---------------------------------------------------------------------------
// HMMA bf16 GEMM mainloop (R15 config): 128x128 block, 8 warps (4m x 2n),
// warp 32x64; single sync per chunk; cp.async double buffer.
// ---------------------------------------------------------------------------
#define KC_ 32
#define NKC_ (D_ / KC_)          // 24
#define TROW_B 80
#define TILE_B (128 * TROW_B)    // 10240
#define BUF_B (4 * TILE_B)       // 40960
#define GEMM_SMEM (2 * BUF_B)    // 81920

template <bool USE_BL>
__device__ __forceinline__ void hmma_mainloop(
        float acc[2][8][4],
        const __nv_bfloat16* __restrict__ Ah, const __nv_bfloat16* __restrict__ Al,
        const __nv_bfloat16* __restrict__ Bh, const __nv_bfloat16* __restrict__ Bl,
        int m0, int n0, char* sm) {
    const int tid = threadIdx.x;
    const int warp = tid >> 5, lane = tid & 31;
    const int wm = warp & 3, wn = warp >> 2;

    const int lr = tid >> 1;
    const int lce = (tid & 1) * 16;
    const uint32_t sto = (uint32_t)lr * TROW_B + (tid & 1) * 32;
    const uint32_t smu = smem_u32(sm);

    const __nv_bfloat16* pAh = Ah + (size_t)(m0 + lr) * D_ + lce;
    const __nv_bfloat16* pAl = Al + (size_t)(m0 + lr) * D_ + lce;
    const __nv_bfloat16* pBh = Bh + (size_t)(n0 + lr) * D_ + lce;
    const __nv_bfloat16* pBl = USE_BL ? (Bl + (size_t)(n0 + lr) * D_ + lce) : pBh;

#define ISSUE(kc, buf) do {                                                  \
    uint32_t _bb = smu + (buf) * BUF_B + sto;                                \
    const int _o = (kc) * KC_;                                               \
    CP16(_bb, pAh + _o);                 CP16(_bb + 16, pAh + _o + 8);       \
    CP16(_bb + TILE_B, pAl + _o);        CP16(_bb + TILE_B + 16, pAl + _o + 8); \
    CP16(_bb + 2 * TILE_B, pBh + _o);    CP16(_bb + 2 * TILE_B + 16, pBh + _o + 8); \
    if (USE_BL) {                                                            \
        CP16(_bb + 3 * TILE_B, pBl + _o);                                    \
        CP16(_bb + 3 * TILE_B + 16, pBl + _o + 8);                           \
    }                                                                        \
    CP_COMMIT(); } while (0)

    ISSUE(0, 0);

    const int arow = (lane & 7) + ((lane >> 3) & 1) * 8;
    const int acolb = (lane >> 4) * 16;
    const int brow = (lane & 7) + (lane >> 4) * 8;
    const int bcolb = ((lane >> 3) & 1) * 16;

    for (int kc = 0; kc < NKC_; ++kc) {
        CP_WAIT0();
        __syncthreads();
        const uint32_t bufb = smu + (kc & 1) * BUF_B;
        const uint32_t aA0 = bufb + (uint32_t)(wm * 32 + arow) * TROW_B + acolb;
        const uint32_t bB0 = bufb + 2 * TILE_B + (uint32_t)(wn * 64 + brow) * TROW_B + bcolb;
#pragma unroll
        for (int ks = 0; ks < 2; ++ks) {
            uint32_t ah[2][4], al[2][4], bh[4][4], bl[4][4];
#pragma unroll
            for (int mf = 0; mf < 2; ++mf) {
                ldsm_x4(ah[mf], aA0 + mf * 16 * TROW_B + ks * 32);
                ldsm_x4(al[mf], aA0 + TILE_B + mf * 16 * TROW_B + ks * 32);
            }
#pragma unroll
            for (int nfp = 0; nfp < 4; ++nfp) {
                ldsm_x4(bh[nfp], bB0 + nfp * 16 * TROW_B + ks * 32);
                if (USE_BL) ldsm_x4(bl[nfp], bB0 + TILE_B + nfp * 16 * TROW_B + ks * 32);
            }
            if (ks == 0 && kc + 1 < NKC_) ISSUE(kc + 1, (kc + 1) & 1);
#pragma unroll
            for (int nfp = 0; nfp < 4; ++nfp)
#pragma unroll
                for (int hf = 0; hf < 2; ++hf) {
                    const int nf = nfp * 2 + hf;
                    const uint32_t b0h = bh[nfp][hf * 2], b1h = bh[nfp][hf * 2 + 1];
#pragma unroll
                    for (int mf = 0; mf < 2; ++mf) {
                        mma16816(acc[mf][nf], ah[mf][0], ah[mf][1], ah[mf][2], ah[mf][3], b0h, b1h);
                        mma16816(acc[mf][nf], al[mf][0], al[mf][1], al[mf][2], al[mf][3], b0h, b1h);
                        if (USE_BL)
                            mma16816(acc[mf][nf], ah[mf][0], ah[mf][1], ah[mf][2], ah[mf][3],
                                     bl[nfp][hf * 2], bl[nfp][hf * 2 + 1]);
                    }
                }
        }
    }
    __syncthreads();
#undef ISSUE
}

// ---------------------------------------------------------------------------
// Combined GEMM kernel (R15 config, 128x128): z=0 -> h GEMM; z=1 -> gate GEMM.
// ---------------------------------------------------------------------------
__global__ __launch_bounds__(256, 2) void gemm_all_kernel(const float* __restrict__ wsrc,
                                                          const float* __restrict__ wdst,
                                                          const float* __restrict__ Hb) {
    extern __shared__ char sm[];
    const int m0 = blockIdx.y << 7;
    const int n0 = blockIdx.x << 7;
    float acc[2][8][4];
#pragma unroll
    for (int mf = 0; mf < 2; ++mf)
#pragma unroll
        for (int nf = 0; nf < 8; ++nf)
#pragma unroll
            for (int q = 0; q < 4; ++q) acc[mf][nf][q] = 0.f;

    const int warp = threadIdx.x >> 5, lane = threadIdx.x & 31;
    const int wm = warp & 3, wn = warp >> 2;
    const int g = lane >> 2, t = lane & 3;

    if (blockIdx.z == 0) {
        hmma_mainloop<true>(acc, g_fh, g_fl, g_w1h, g_w1l, m0, n0, sm);
        const int head = (n0 >> 6) + wn;
        float sd[2][2], dd[2][2];
#pragma unroll
        for (int mf = 0; mf < 2; ++mf) sd[mf][0] = sd[mf][1] = dd[mf][0] = dd[mf][1] = 0.f;
#pragma unroll
        for (int mf = 0; mf < 2; ++mf) {
            const int m = m0 + wm * 32 + mf * 16 + g;
            const int b = m >> 9, i = m & (N_ - 1);
            const int ba = b * A_ + head;
#pragma unroll
            for (int nf = 0; nf < 8; ++nf) {
                const int e = nf * 8 + 2 * t;
                __nv_bfloat16 h0, l0, h1, l1;
                split2(acc[mf][nf][0], h0, l0);
                split2(acc[mf][nf][1], h1, l1);
                *(__nv_bfloat162*)&g_hbh[((size_t)(ba * N_ + i)) * E_ + e] = __nv_bfloat162(h0, h1);
                *(__nv_bfloat162*)&g_hbl[((size_t)(ba * N_ + i)) * E_ + e] = __nv_bfloat162(l0, l1);
                split2(acc[mf][nf][2], h0, l0);
                split2(acc[mf][nf][3], h1, l1);
                *(__nv_bfloat162*)&g_hbh[((size_t)(ba * N_ + i + 8)) * E_ + e] = __nv_bfloat162(h0, h1);
                *(__nv_bfloat162*)&g_hbl[((size_t)(ba * N_ + i + 8)) * E_ + e] = __nv_bfloat162(l0, l1);
                float2 ws = *(const float2*)(wsrc + head * E_ + e);
                float2 wd = *(const float2*)(wdst + head * E_ + e);
                float t0 = tanhf(acc[mf][nf][0]), t1 = tanhf(acc[mf][nf][1]);
                float t2 = tanhf(acc[mf][nf][2]), t3 = tanhf(acc[mf][nf][3]);
                sd[mf][0] += t0 * ws.x + t1 * ws.y;
                sd[mf][1] += t2 * ws.x + t3 * ws.y;
                dd[mf][0] += t0 * wd.x + t1 * wd.y;
                dd[mf][1] += t2 * wd.x + t3 * wd.y;
            }
#pragma unroll
            for (int rh = 0; rh < 2; ++rh) {
                float s = sd[mf][rh], d = dd[mf][rh];
                s += __shfl_xor_sync(0xffffffffu, s, 1);
                s += __shfl_xor_sync(0xffffffffu, s, 2);
                d += __shfl_xor_sync(0xffffffffu, d, 1);
                d += __shfl_xor_sync(0xffffffffu, d, 2);
                if (t == 0) {
                    g_src[ba * N_ + i + rh * 8] = s;
                    g_dst[ba * N_ + i + rh * 8] = d;
                }
            }
        }
    } else {
        hmma_mainloop<false>(acc, g_fh, g_fl, g_w2h, g_w2h, m0, n0, sm);
#pragma unroll
        for (int mf = 0; mf < 2; ++mf)
#pragma unroll
            for (int nf = 0; nf < 8; ++nf) {
                const int m = m0 + wm * 32 + mf * 16 + g;
                const int n = n0 + wn * 64 + nf * 8 + 2 * t;
                float2 hb = *(const float2*)(Hb + n);
#pragma unroll
                for (int rr = 0; rr < 2; ++rr) {
                    const int mm = m + rr * 8;
                    float2 gv;
                    gv.x = 1.f / (1.f + __expf(-(acc[mf][nf][rr * 2 + 0] + hb.x)));
                    gv.y = 1.f / (1.f + __expf(-(acc[mf][nf][rr * 2 + 1] + hb.y)));
                    *(float2*)(g_gate + (size_t)mm * D_ + n) = gv;
                }
            }
    }
}

// ---------------------------------------------------------------------------
// Attention (R16 config: i-tile 64, double-buffered P, 1 sync/chunk,
// pgen overlapped with MMA) + fused highway blend epilogue.
// ---------------------------------------------------------------------------
#define IT_ 64
#define HC_ROWB 144
#define HC_BUF_B (64 * HC_ROWB)          // 9216
#define P_ROWB 144
#define P_BUF_B (64 * P_ROWB)            // 9216
#define OFF_HCH 0                        // 2 bufs: 18432
#define OFF_HCL 18432                    // 2 bufs: 18432
#define OFF_PBH 36864                    // 2 bufs: 18432
#define OFF_PBL 55296                    // 2 bufs: 18432
#define OFF_SRC 73728                    // 256
#define OFF_DST 73984                    // 2048
#define OFF_MS  76032                    // 4096
#define OFF_SUM 80128                    // 256
#define ATT_SMEM_B 80384

__global__ __launch_bounds__(256, 2) void attn_kernel(const void* __restrict__ adjv,
                                                      const float* __restrict__ bbias,
                                                      const float* __restrict__ feat,
                                                      float* __restrict__ out) {
    extern __shared__ char sm[];
    const uint32_t smu = smem_u32(sm);
    char* Pbh = sm + OFF_PBH;
    char* Pbl = sm + OFF_PBL;
    float* s_src = (float*)(sm + OFF_SRC);
    float* s_dst = (float*)(sm + OFF_DST);
    float* s_sum = (float*)(sm + OFF_SUM);
    unsigned short* Ms = (unsigned short*)(sm + OFF_MS);   // [32 jwords][64 rows]

    const int tid = threadIdx.x;
    const int lane = tid & 31, warp = tid >> 5;
    const int b = blockIdx.z, a = blockIdx.y, it = blockIdx.x;
    const int ba = b * A_ + a;
    const int i0 = it * IT_;

    const __nv_bfloat16* srcH = g_hbh + (size_t)ba * N_ * E_;
    const __nv_bfloat16* srcL = g_hbl + (size_t)ba * N_ * E_;

#define ISSUE_H(jc, buf) do {                                                \
    const int _j0 = (jc) * 64;                                               \
    _Pragma("unroll")                                                        \
    for (int _c = 0; _c < 2; ++_c) {                                         \
        const int _idx = tid * 2 + _c;                                       \
        const int _jr = _idx >> 3, _q = _idx & 7;                            \
        const uint32_t _dst = smu + OFF_HCH + (buf) * HC_BUF_B + _jr * HC_ROWB + _q * 16; \
        CP16(_dst, srcH + (size_t)(_j0 + _jr) * E_ + _q * 8);                \
        CP16(_dst + (OFF_HCL - OFF_HCH), srcL + (size_t)(_j0 + _jr) * E_ + _q * 8); \
    }                                                                        \
    CP_COMMIT(); } while (0)

    // ---- Phase A ----
    ISSUE_H(0, 0);
    if (tid < IT_) s_src[tid] = g_src[ba * N_ + i0 + tid];
    s_dst[tid] = g_dst[ba * N_ + tid];
    s_dst[tid + 256] = g_dst[ba * N_ + tid + 256];
    __syncthreads();

    // ---- Phase B: mask bits ----
    const int adj_int = g_adj_int;
    for (int rr = warp; rr < IT_; rr += 8) {
        const size_t rowoff = (size_t)(b * N_ + i0 + rr) * N_;
        unsigned mbits = 0;
        if (adj_int) {
            const uint4* ap = (const uint4*)((const int*)adjv + rowoff + lane * 16);
#pragma unroll
            for (int q = 0; q < 4; ++q) {
                uint4 w = ap[q];
                mbits |= (w.x ? 1u : 0u) << (q * 4 + 0);
                mbits |= (w.y ? 1u : 0u) << (q * 4 + 1);
                mbits |= (w.z ? 1u : 0u) << (q * 4 + 2);
                mbits |= (w.w ? 1u : 0u) << (q * 4 + 3);
            }
        } else {
            uint4 w = *(const uint4*)((const uint8_t*)adjv + rowoff + lane * 16);
            unsigned ws[4] = {w.x, w.y, w.z, w.w};
#pragma unroll
            for (int q = 0; q < 4; ++q)
#pragma unroll
                for (int bq = 0; bq < 4; ++bq)
                    mbits |= (((ws[q] >> (8 * bq)) & 0xffu) ? 1u : 0u) << (q * 4 + bq);
        }
        Ms[lane * IT_ + rr] = (unsigned short)mbits;
    }
    __syncthreads();

    // ---- Phase C: pipelined P-gen / HMMA ----
    const int wm = warp & 1, wn = warp >> 1;
    const int r = tid >> 2, jseg = (tid & 3) * 16;
    const float srcv = s_src[r];

    const int arow = (lane & 7) + ((lane >> 3) & 1) * 8;
    const int acolb = (lane >> 4) * 16;
    const uint32_t aP0 = smu + OFF_PBH + (uint32_t)(wm * 32 + arow) * P_ROWB + acolb;
    const int jrow = lane & 15;
    const int ecolb = (lane >> 4) * 16;
    const uint32_t bH0 = smu + OFF_HCH + (uint32_t)jrow * HC_ROWB + (wn * 16) * 2 + ecolb;

    float acc[2][2][4];
#pragma unroll
    for (int mf = 0; mf < 2; ++mf)
#pragma unroll
        for (int nf = 0; nf < 2; ++nf)
#pragma unroll
            for (int q = 0; q < 4; ++q) acc[mf][nf][q] = 0.f;

    float psum = 0.f;

    auto pgen = [&](int jc, int buf) {
        const int jb = jc * 64 + jseg;
        uint32_t mbits = Ms[(jb >> 4) * IT_ + r];
        char* ph = Pbh + buf * P_BUF_B + r * P_ROWB;
        char* pl = Pbl + buf * P_BUF_B + r * P_ROWB;
#pragma unroll
        for (int q = 0; q < 16; q += 4) {
            float4 dv = *(const float4*)&s_dst[jb + q];
            float p[4];
#pragma unroll
            for (int e = 0; e < 4; ++e) {
                float v = srcv + (&dv.x)[e];
                v = v >= 0.f ? v : 0.2f * v;
                p[e] = ((mbits >> (q + e)) & 1u) ? __expf(v) : 0.f;
                psum += p[e];
            }
            __nv_bfloat16 h0, l0, h1, l1;
            split2(p[0], h0, l0); split2(p[1], h1, l1);
            *(__nv_bfloat162*)(ph + (jseg + q) * 2) = __nv_bfloat162(h0, h1);
            *(__nv_bfloat162*)(pl + (jseg + q) * 2) = __nv_bfloat162(l0, l1);
            split2(p[2], h0, l0); split2(p[3], h1, l1);
            *(__nv_bfloat162*)(ph + (jseg + q + 2) * 2) = __nv_bfloat162(h0, h1);
            *(__nv_bfloat162*)(pl + (jseg + q + 2) * 2) = __nv_bfloat162(l0, l1);
        }
    };

    pgen(0, 0);

    for (int jc = 0; jc < 8; ++jc) {
        CP_WAIT0();            // own copies of H[jc] done
        __syncthreads();       // everyone's copies done; prior reads of opposite bufs retired
        if (jc + 1 < 8) {
            ISSUE_H(jc + 1, (jc + 1) & 1);
            pgen(jc + 1, (jc + 1) & 1);
        }
        const uint32_t pb = (jc & 1) * P_BUF_B;
        const uint32_t bbuf = bH0 + (jc & 1) * HC_BUF_B;
#pragma unroll
        for (int ks = 0; ks < 4; ++ks) {
            uint32_t ah[2][4], al[2][4], bh[4], bl[4];
#pragma unroll
            for (int mf = 0; mf < 2; ++mf) {
                ldsm_x4(ah[mf], aP0 + pb + mf * 16 * P_ROWB + ks * 32);
                ldsm_x4(al[mf], aP0 + pb + (OFF_PBL - OFF_PBH) + mf * 16 * P_ROWB + ks * 32);
            }
            const uint32_t bbase = bbuf + (uint32_t)(ks * 16) * HC_ROWB;
            ldsm_x4_t(bh, bbase);
            ldsm_x4_t(bl, bbase + (OFF_HCL - OFF_HCH));
#pragma unroll
            for (int nf = 0; nf < 2; ++nf) {
                const uint32_t b0h = bh[nf * 2], b1h = bh[nf * 2 + 1];
                const uint32_t b0l = bl[nf * 2], b1l = bl[nf * 2 + 1];
#pragma unroll
                for (int mf = 0; mf < 2; ++mf) {
                    mma16816(acc[mf][nf], ah[mf][0], ah[mf][1], ah[mf][2], ah[mf][3], b0h, b1h);
                    mma16816(acc[mf][nf], al[mf][0], al[mf][1], al[mf][2], al[mf][3], b0h, b1h);
                    mma16816(acc[mf][nf], ah[mf][0], ah[mf][1], ah[mf][2], ah[mf][3], b0l, b1l);
                }
            }
        }
    }
#undef ISSUE_H

    // row-sum: quad-reduce and publish
    psum += __shfl_xor_sync(0xffffffffu, psum, 1);
    psum += __shfl_xor_sync(0xffffffffu, psum, 2);
    if ((tid & 3) == 0) s_sum[r] = psum;
    __syncthreads();

    // ---- epilogue: normalize + bias + elu + highway blend -> d_out ----
    const int g = lane >> 2, t = lane & 3;
#pragma unroll
    for (int mf = 0; mf < 2; ++mf) {
        const int rl = wm * 32 + mf * 16 + g;
        const float inv0 = __fdividef(1.f, s_sum[rl]);
        const float inv1 = __fdividef(1.f, s_sum[rl + 8]);
#pragma unroll
        for (int nf = 0; nf < 2; ++nf) {
            const int col = wn * 16 + nf * 8 + 2 * t;
            const int n = a * E_ + col;
            float2 bias = *(const float2*)(bbias + col);
#pragma unroll
            for (int rr = 0; rr < 2; ++rr) {
                const int row = i0 + rl + rr * 8;
                const size_t off = (size_t)(b * N_ + row) * D_ + n;
                const float inv = rr ? inv1 : inv0;
                float2 gv = *(const float2*)(g_gate + off);
                float2 fv = *(const float2*)(feat + off);
                float a0 = fmaf(acc[mf][nf][rr * 2 + 0], inv, bias.x);
                float a1 = fmaf(acc[mf][nf][rr * 2 + 1], inv, bias.y);
                float fo0 = a0 > 0.f ? a0 : (__expf(a0) - 1.f);
                float fo1 = a1 > 0.f ? a1 : (__expf(a1) - 1.f);
                float2 ov;
                ov.x = gv.x * fo0 + (1.f - gv.x) * fv.x;
                ov.y = gv.y * fo1 + (1.f - gv.y) * fv.y;
                *(float2*)(out + off) = ov;
            }
        }
    }
}

// ---------------------------------------------------------------------------
extern "C" void kernel_launch(void* const* d_in, const int* in_sizes, int n_in,
                              void* d_out, int out_size) {
    const float* feat = (const float*)d_in[0];
    const void* adj = d_in[1];
    const float* W = (const float*)d_in[2];
    const float* bbias = (const float*)d_in[3];
    const float* wsrc = (const float*)d_in[4];
    const float* wdst = (const float*)d_in[5];
    const float* Hw = (const float*)d_in[6];
    const float* Hb = (const float*)d_in[7];
    float* out = (float*)d_out;

    prep_kernel<<<PREP_GRID, 256>>>(feat, W, Hw, (const int*)adj);

    cudaFuncSetAttribute(gemm_all_kernel, cudaFuncAttributeMaxDynamicSharedMemorySize, GEMM_SMEM);
    cudaFuncSetAttribute(attn_kernel, cudaFuncAttributeMaxDynamicSharedMemorySize, ATT_SMEM_B);

    gemm_all_kernel<<<dim3(D_ / 128, M_ / 128, 2), 256, GEMM_SMEM>>>(wsrc, wdst, Hb);

    attn_kernel<<<dim3(N_ / IT_, A_, B_), 256, ATT_SMEM_B>>>(adj, bbias, feat, out);
}